// round 14
// baseline (speedup 1.0000x reference)
#include <cuda_runtime.h>
#include <cstdint>

// Problem constants (fixed by the dataset)
#define BATCH      16
#define NPTS       131072
#define KCENT      1024
#define NBLK       8                    // blocks cooperating per batch
#define CHUNK      (NPTS / NBLK)        // 16384 points per block
#define THREADS    1024
#define PT_PER_T   (CHUNK / THREADS)    // 16 dist values in registers per thread
#define GROUPS     (PT_PER_T / 4)       // 4 float4 groups per thread
#define NWARP      (THREADS / 32)       // 32

typedef unsigned long long u64;

// Cross-CTA exchange: 4 self-verifying words per CTA, parity double-buffered.
//   word0 = [distbits:32 | (idx^0x1FFFF):17 | seq:15]
//   word1..3 = [float bits of x/y/z : 32 | seq:32]
// seq = k+1. A word is valid iff its seq matches the target -> no atomics,
// fences or counters; stale values can never alias a fresh seq.
__device__ u64 g_slot[BATCH][2][NBLK][4];

__global__ void __launch_bounds__(THREADS, 1)
fps_kernel(const float* __restrict__ pt, float* __restrict__ out) {
    const int blk = blockIdx.x;        // 0..127
    const int b   = blk / NBLK;        // batch
    const int sub = blk % NBLK;        // sub-block within batch
    const int tid = threadIdx.x;
    const int wid = tid >> 5;
    const int lid = tid & 31;

    __shared__ u64 s_red[NWARP];

    const float* px_g = pt + (size_t)b * 3 * NPTS;
    const float* py_g = px_g + NPTS;
    const float* pz_g = px_g + 2 * NPTS;
    const int base = sub * CHUNK;

    const float4* __restrict__ gx = reinterpret_cast<const float4*>(px_g + base);
    const float4* __restrict__ gy = reinterpret_cast<const float4*>(py_g + base);
    const float4* __restrict__ gz = reinterpret_cast<const float4*>(pz_g + base);

    // ---- register-resident min-distance array
    float dist[PT_PER_T];
#pragma unroll
    for (int i = 0; i < PT_PER_T; i++) dist[i] = __int_as_float(0x7f800000);  // +inf

    // Centroid state lives in registers in EVERY thread (no smem broadcast).
    int   cur = 0;
    float cx = px_g[0], cy = py_g[0], cz = pz_g[0];   // broadcast L1 loads

    for (int k = 0; k < KCENT; k++) {
        const int p = k & 1;

        // Output dtype is float32; indices < 2^24 are exact.
        if (sub == 0 && tid == 0) out[b * KCENT + k] = (float)cur;

        // ---- update dists & local argmax (bit-exact scalar math, rel_err 0.0)
        float best_d = -1.0f;
        int   best_i = 0;
#pragma unroll
        for (int g = 0; g < GROUPS; g++) {
            const int vi = g * THREADS + tid;
            const float4 x4 = gx[vi];
            const float4 y4 = gy[vi];
            const float4 z4 = gz[vi];
            const int p0 = base + vi * 4;
            const float xs[4] = {x4.x, x4.y, x4.z, x4.w};
            const float ys[4] = {y4.x, y4.y, y4.z, y4.w};
            const float zs[4] = {z4.x, z4.y, z4.z, z4.w};
#pragma unroll
            for (int j = 0; j < 4; j++) {
                const float dx = __fadd_rn(xs[j], -cx);
                const float dy = __fadd_rn(ys[j], -cy);
                const float dz = __fadd_rn(zs[j], -cz);
                const float d  = __fadd_rn(__fadd_rn(__fmul_rn(dx, dx),
                                                     __fmul_rn(dy, dy)),
                                           __fmul_rn(dz, dz));
                const float nd = fminf(dist[g * 4 + j], d);
                dist[g * 4 + j] = nd;
                if (nd > best_d) { best_d = nd; best_i = p0 + j; }
            }
        }

        // ---- pack (dist, ~idx): max over packed == max dist, ties -> lowest idx.
        u64 key = ((u64)__float_as_uint(best_d) << 32) |
                  (unsigned)(~(unsigned)best_i);

        // warp reduce
#pragma unroll
        for (int off = 16; off > 0; off >>= 1) {
            u64 o = __shfl_down_sync(0xffffffffu, key, off);
            if (o > key) key = o;
        }
        if (lid == 0) s_red[wid] = key;
        __syncthreads();           // the ONLY block barrier per iteration

        // ---- warp 0: block reduce + publish (lanes 0..3)
        if (wid == 0) {
            u64 v = s_red[lid];                        // NWARP == 32
#pragma unroll
            for (int off = 16; off > 0; off >>= 1) {
                u64 o = __shfl_down_sync(0xffffffffu, v, off);
                if (o > v) v = o;
            }
            const u64 bb = __shfl_sync(0xffffffffu, v, 0);
            const unsigned seq = (unsigned)(k + 1);

            if (lid < 4) {
                u64 w;
                if (lid == 0) {
                    const unsigned distb = (unsigned)(bb >> 32);
                    const unsigned idx   = ~(unsigned)bb;           // 17 bits
                    w = ((u64)distb << 32) |
                        ((u64)((idx ^ 0x1FFFFu) & 0x1FFFFu) << 15) | seq;
                } else {
                    const int bi = (int)(~(unsigned)bb);
                    const float c = px_g[(size_t)(lid - 1) * NPTS + bi];  // L1 hit
                    w = ((u64)__float_as_uint(c) << 32) | seq;
                }
                asm volatile("st.relaxed.gpu.u64 [%0], %1;"
                             :: "l"(&g_slot[b][p][sub][lid]), "l"(w) : "memory");
            }
        }

        // ---- EVERY warp polls the 8x4 words autonomously (lane l -> CTA l>>2,
        // word l&3), extracts the winner, and proceeds straight into the next
        // distance pass. No second barrier, no smem broadcast.
        {
            const unsigned seq = (unsigned)(k + 1);
            const int rr = lid >> 2, ww = lid & 3;
            const u64* addr = &g_slot[b][p][rr][ww];
            u64 wv = 0;
            int t = 0;
            for (;;) {
                asm volatile("ld.relaxed.gpu.u64 %0, [%1];"
                             : "=l"(wv) : "l"(addr) : "memory");
                const unsigned got = (ww == 0) ? (unsigned)(wv & 0x7FFFu)
                                               : (unsigned)wv;
                if (got == seq || ++t >= (1 << 20)) break;
            }

            // max over the 8 key words (lanes 0,4,...,28); others contribute 0
            u64 m = (ww == 0) ? wv : 0ull;
#pragma unroll
            for (int off = 4; off <= 16; off <<= 1) {
                u64 o = __shfl_xor_sync(0xffffffffu, m, off);
                if (o > m) m = o;
            }
            const u64 gk = __shfl_sync(0xffffffffu, m, 0);

            // winner CTA: exactly one key lane matches (indices unique)
            const unsigned mk  = __ballot_sync(0xffffffffu, (ww == 0) && (wv == gk));
            const int      src = __ffs(mk) - 1;                    // = 4 * winner_rank
            cx  = __uint_as_float((unsigned)(__shfl_sync(0xffffffffu, wv, src + 1) >> 32));
            cy  = __uint_as_float((unsigned)(__shfl_sync(0xffffffffu, wv, src + 2) >> 32));
            cz  = __uint_as_float((unsigned)(__shfl_sync(0xffffffffu, wv, src + 3) >> 32));
            cur = (int)((((unsigned)(gk >> 15)) & 0x1FFFFu) ^ 0x1FFFFu);
        }
    }
}

extern "C" void kernel_launch(void* const* d_in, const int* in_sizes, int n_in,
                              void* d_out, int out_size) {
    // Select the coordinate buffer by SIZE, not position: pt has 6291456 elements.
    const float* ptc = nullptr;
    for (int i = 0; i < n_in; i++) {
        if (in_sizes[i] == BATCH * 3 * NPTS) { ptc = (const float*)d_in[i]; break; }
    }
    if (!ptc) {  // fallback: largest input
        int bi = 0;
        for (int i = 1; i < n_in; i++) if (in_sizes[i] > in_sizes[bi]) bi = i;
        ptc = (const float*)d_in[bi];
    }
    float* out = (float*)d_out;
    (void)out_size;

    fps_kernel<<<BATCH * NBLK, THREADS>>>(ptc, out);
}

// round 15
// speedup vs baseline: 1.3924x; 1.3924x over previous
#include <cuda_runtime.h>
#include <cstdint>

// Problem constants (fixed by the dataset)
#define BATCH      16
#define NPTS       131072
#define KCENT      1024
#define NBLK       8                    // blocks cooperating per batch
#define CHUNK      (NPTS / NBLK)        // 16384 points per block
#define THREADS    1024
#define PT_PER_T   (CHUNK / THREADS)    // 16 dist values in registers per thread
#define GROUPS     (PT_PER_T / 4)       // 4 float4 groups per thread
#define NWARP      (THREADS / 32)       // 32

typedef unsigned long long u64;

// Cross-CTA exchange: 4 self-verifying words per CTA, parity double-buffered.
//   word0 = [distbits:32 | (idx^0x1FFFF):17 | seq:15]
//   word1..3 = [float bits of x/y/z : 32 | seq:32]
// seq = k+1. A word is valid iff its seq matches the target -> no atomics,
// fences or counters; stale values can never alias a fresh seq.
__device__ u64 g_slot[BATCH][2][NBLK][4];

__global__ void __launch_bounds__(THREADS, 1)
fps_kernel(const float* __restrict__ pt, float* __restrict__ out) {
    const int blk = blockIdx.x;        // 0..127
    const int b   = blk / NBLK;        // batch
    const int sub = blk % NBLK;        // sub-block within batch
    const int tid = threadIdx.x;
    const int wid = tid >> 5;
    const int lid = tid & 31;

    extern __shared__ float smem[];    // 3*CHUNK floats = 196608 B
    float* sx = smem;
    float* sy = smem + CHUNK;
    float* sz = smem + 2 * CHUNK;

    __shared__ u64   s_red[NWARP];
    __shared__ float s_p[3];
    __shared__ int   s_cur;

    const float* px_g = pt + (size_t)b * 3 * NPTS;
    const float* py_g = px_g + NPTS;
    const float* pz_g = px_g + 2 * NPTS;
    const int base = sub * CHUNK;

    // ---- one-time load of this block's chunk into SMEM (vectorized).
    // LDS (29 cyc, own crossbar) replaces LDG-L1 (~39 cyc + L1tex queue shared
    // by 32 warps) in the hot loop; everything else identical to the R12 best.
    {
        const float4* gx = reinterpret_cast<const float4*>(px_g + base);
        const float4* gy = reinterpret_cast<const float4*>(py_g + base);
        const float4* gz = reinterpret_cast<const float4*>(pz_g + base);
        float4* lx = reinterpret_cast<float4*>(sx);
        float4* ly = reinterpret_cast<float4*>(sy);
        float4* lz = reinterpret_cast<float4*>(sz);
        for (int i = tid; i < CHUNK / 4; i += THREADS) {
            lx[i] = gx[i];
            ly[i] = gy[i];
            lz[i] = gz[i];
        }
    }

    // ---- register-resident min-distance array
    float dist[PT_PER_T];
#pragma unroll
    for (int i = 0; i < PT_PER_T; i++) dist[i] = __int_as_float(0x7f800000);  // +inf

    if (tid == 0) {
        s_cur  = 0;
        s_p[0] = px_g[0];
        s_p[1] = py_g[0];
        s_p[2] = pz_g[0];
    }
    __syncthreads();

    for (int k = 0; k < KCENT; k++) {
        const int   cur = s_cur;
        const float cx = s_p[0], cy = s_p[1], cz = s_p[2];
        const int   p  = k & 1;

        // Output dtype is float32; indices < 2^24 are exact.
        if (sub == 0 && tid == 0) out[b * KCENT + k] = (float)cur;

        // ---- update dists & local argmax (bit-exact scalar math, rel_err 0.0)
        float best_d = -1.0f;
        int   best_i = 0;
#pragma unroll
        for (int g = 0; g < GROUPS; g++) {
            const int vi = g * THREADS + tid;
            const float4 x4 = reinterpret_cast<const float4*>(sx)[vi];
            const float4 y4 = reinterpret_cast<const float4*>(sy)[vi];
            const float4 z4 = reinterpret_cast<const float4*>(sz)[vi];
            const int p0 = base + vi * 4;
            const float xs[4] = {x4.x, x4.y, x4.z, x4.w};
            const float ys[4] = {y4.x, y4.y, y4.z, y4.w};
            const float zs[4] = {z4.x, z4.y, z4.z, z4.w};
#pragma unroll
            for (int j = 0; j < 4; j++) {
                const float dx = __fadd_rn(xs[j], -cx);
                const float dy = __fadd_rn(ys[j], -cy);
                const float dz = __fadd_rn(zs[j], -cz);
                const float d  = __fadd_rn(__fadd_rn(__fmul_rn(dx, dx),
                                                     __fmul_rn(dy, dy)),
                                           __fmul_rn(dz, dz));
                const float nd = fminf(dist[g * 4 + j], d);
                dist[g * 4 + j] = nd;
                if (nd > best_d) { best_d = nd; best_i = p0 + j; }
            }
        }

        // ---- pack (dist, ~idx): max over packed == max dist, ties -> lowest idx.
        u64 key = ((u64)__float_as_uint(best_d) << 32) |
                  (unsigned)(~(unsigned)best_i);

        // warp reduce
#pragma unroll
        for (int off = 16; off > 0; off >>= 1) {
            u64 o = __shfl_down_sync(0xffffffffu, key, off);
            if (o > key) key = o;
        }
        if (lid == 0) s_red[wid] = key;
        __syncthreads();

        // ---- warp 0 only: block reduce + one-round-trip cross-CTA exchange
        if (wid == 0) {
            u64 v = s_red[lid];                        // NWARP == 32
#pragma unroll
            for (int off = 16; off > 0; off >>= 1) {
                u64 o = __shfl_down_sync(0xffffffffu, v, off);
                if (o > v) v = o;
            }
            const u64 bb = __shfl_sync(0xffffffffu, v, 0);
            const unsigned seq = (unsigned)(k + 1);

            // lanes 0..3 publish this CTA's 4 words (coords come from own SMEM chunk)
            if (lid < 4) {
                u64 w;
                if (lid == 0) {
                    const unsigned distb = (unsigned)(bb >> 32);
                    const unsigned idx   = ~(unsigned)bb;           // 17 bits
                    w = ((u64)distb << 32) |
                        ((u64)((idx ^ 0x1FFFFu) & 0x1FFFFu) << 15) | seq;
                } else {
                    const int bi = (int)(~(unsigned)bb) - base;     // local index
                    const float c = smem[(size_t)(lid - 1) * CHUNK + bi];
                    w = ((u64)__float_as_uint(c) << 32) | seq;
                }
                asm volatile("st.relaxed.gpu.u64 [%0], %1;"
                             :: "l"(&g_slot[b][p][sub][lid]), "l"(w) : "memory");
            }

            // all 32 lanes of warp0 poll: lane l owns word (l&3) of CTA (l>>2)
            const int rr = lid >> 2, ww = lid & 3;
            const u64* addr = &g_slot[b][p][rr][ww];
            u64 wv = 0;
            int t = 0;
            for (;;) {
                asm volatile("ld.relaxed.gpu.u64 %0, [%1];"
                             : "=l"(wv) : "l"(addr) : "memory");
                const unsigned got = (ww == 0) ? (unsigned)(wv & 0x7FFFu)
                                               : (unsigned)wv;
                if (got == seq || ++t >= (1 << 20)) break;
            }

            // max over the 8 key words (lanes 0,4,...,28); others contribute 0
            u64 m = (ww == 0) ? wv : 0ull;
#pragma unroll
            for (int off = 4; off <= 16; off <<= 1) {
                u64 o = __shfl_xor_sync(0xffffffffu, m, off);
                if (o > m) m = o;
            }
            const u64 gk = __shfl_sync(0xffffffffu, m, 0);

            // winner CTA: exactly one key lane matches (indices unique)
            const unsigned mk  = __ballot_sync(0xffffffffu, (ww == 0) && (wv == gk));
            const int      src = __ffs(mk) - 1;                    // = 4 * winner_rank
            const float xx = __uint_as_float((unsigned)(__shfl_sync(0xffffffffu, wv, src + 1) >> 32));
            const float yy = __uint_as_float((unsigned)(__shfl_sync(0xffffffffu, wv, src + 2) >> 32));
            const float zz = __uint_as_float((unsigned)(__shfl_sync(0xffffffffu, wv, src + 3) >> 32));
            const int nxt = (int)((((unsigned)(gk >> 15)) & 0x1FFFFu) ^ 0x1FFFFu);

            if (lid == 0) {
                s_cur  = nxt;
                s_p[0] = xx;
                s_p[1] = yy;
                s_p[2] = zz;
            }
        }
        __syncthreads();
    }
}

extern "C" void kernel_launch(void* const* d_in, const int* in_sizes, int n_in,
                              void* d_out, int out_size) {
    // Select the coordinate buffer by SIZE, not position: pt has 6291456 elements.
    const float* ptc = nullptr;
    for (int i = 0; i < n_in; i++) {
        if (in_sizes[i] == BATCH * 3 * NPTS) { ptc = (const float*)d_in[i]; break; }
    }
    if (!ptc) {  // fallback: largest input
        int bi = 0;
        for (int i = 1; i < n_in; i++) if (in_sizes[i] > in_sizes[bi]) bi = i;
        ptc = (const float*)d_in[bi];
    }
    float* out = (float*)d_out;
    (void)out_size;

    const int smem_bytes = 3 * CHUNK * sizeof(float);  // 196608 B
    cudaFuncSetAttribute(fps_kernel,
                         cudaFuncAttributeMaxDynamicSharedMemorySize,
                         smem_bytes);

    fps_kernel<<<BATCH * NBLK, THREADS, smem_bytes>>>(ptc, out);
}